// round 13
// baseline (speedup 1.0000x reference)
#include <cuda_runtime.h>

#define BB 64
#define TT 512
#define HH 768
#define LL 9
#define AST 12
#define NG 10
#define NGEMM 1024
#define LOG2E 1.4426950408889634f
#define LN2   0.6931471805599453f

__device__ __align__(16) float g_logits[BB * TT * LL];
__device__ float g_ll[BB];
__device__ float g_part[BB][4];   // per-block tp,tn,fp,corr (overwritten each run)
__device__ int   g_flag[BB * 16]; // per (batch,chunk) ready flags (reset by last block)
__device__ int   g_tick;          // ticket (reset by last block)

__device__ __forceinline__ float ex2f_(float x) {
    float y; asm("ex2.approx.ftz.f32 %0, %1;" : "=f"(y) : "f"(x)); return y;
}
__device__ __forceinline__ float lg2f_(float x) {
    float y; asm("lg2.approx.ftz.f32 %0, %1;" : "=f"(y) : "f"(x)); return y;
}
__device__ __forceinline__ int wredi(int v) {
    #pragma unroll
    for (int o = 16; o; o >>= 1) v += __shfl_xor_sync(0xffffffffu, v, o);
    return v;
}
__device__ __forceinline__ float wredf(float v) {
    #pragma unroll
    for (int o = 16; o; o >>= 1) v += __shfl_xor_sync(0xffffffffu, v, o);
    return v;
}

#define MAP_IDENTITY 0x876543210ull
__device__ __forceinline__ unsigned long long map_compose(unsigned long long F,
                                                          unsigned long long G) {
    unsigned long long h = 0;
    #pragma unroll
    for (int i = 0; i < 9; i++) {
        int gi = (int)((G >> (4 * i)) & 15ull);
        unsigned long long fi = (F >> (gi * 4)) & 15ull;
        h |= fi << (4 * i);
    }
    return h;
}

// NOTE: sPp placed at a 16B-aligned offset (before Ts) — it is float4-loaded.
struct CrfSmem {
    float slog[TT * LL];          // off 0      (18432 B)
    float astore[TT * AST];       // off 18432  (24576 B), rows 48 B
    float swexp[TT * LL];         // off 43008  (18432 B)
    float sPp[LL * 12];           // off 61440  -- 16B-aligned, float4-loadable
    float Ts[LL * LL];            // scalar access only
    float sM[NG][LL][LL];
    int   sE[NG][LL];
    int   sEg[NG];
    unsigned char sbp[TT * LL];
    unsigned char stag[TT];
    int   s_cflag[16];
    float s_logZ;
    int   s_lasti;
    int   s_isLast;
    int   sh_m[4][8];
};
struct GemmSmem {
    float Ws[HH * 12];            // padded W rows (48 B, float4-loadable)
    float bs[LL];
};

// ---------------------------------------------------------------------------
// Fused kernel. bids 0..63: CRF (batch=bid). bids 64..1087: GEMM chunk-major.
// ---------------------------------------------------------------------------
__global__ void __launch_bounds__(256, 3)
fused_kernel(const float* __restrict__ x, const float* __restrict__ W,
             const float* __restrict__ bias, const float* __restrict__ trans,
             const int* __restrict__ label, const int* __restrict__ seqlen,
             float* __restrict__ outF) {
    extern __shared__ __align__(16) char smem_raw[];
    int bid = blockIdx.x;
    int tid = threadIdx.x, lane = tid & 31, warp = tid >> 5;

    if (bid >= BB) {
        // ==================== GEMM role ====================
        GemmSmem* G = (GemmSmem*)smem_raw;
        int g = bid - BB;
        int c = g >> 6, bb = g & 63;

        for (int i = tid; i < HH * 12; i += 256) {
            int h = i / 12, l = i - h * 12;
            G->Ws[i] = (l < LL) ? W[h * LL + l] : 0.0f;
        }
        if (tid < LL) G->bs[tid] = bias[tid];
        __syncthreads();

        int row0 = bb * TT + c * 32 + warp * 4;
        const float* xp = x + (size_t)row0 * HH;

        unsigned long long acc[4][5];
        #pragma unroll
        for (int r = 0; r < 4; r++)
            #pragma unroll
            for (int p = 0; p < 5; p++) acc[r][p] = 0ull;

        #pragma unroll
        for (int kk = 0; kk < 6; kk++) {
            int h0 = lane * 4 + 128 * kk;
            float4 xr[4];
            xr[0] = *(const float4*)(xp + h0);
            xr[1] = *(const float4*)(xp + HH + h0);
            xr[2] = *(const float4*)(xp + 2 * HH + h0);
            xr[3] = *(const float4*)(xp + 3 * HH + h0);
            #pragma unroll
            for (int d = 0; d < 4; d++) {
                const float* wr = G->Ws + (h0 + d) * 12;
                float4 wa = *(const float4*)(wr);
                float4 wb = *(const float4*)(wr + 4);
                float  w8 = wr[8];
                unsigned long long w0, w1, w2, w3, w4p;
                asm("mov.b64 %0, {%1,%2};" : "=l"(w0) : "f"(wa.x), "f"(wa.y));
                asm("mov.b64 %0, {%1,%2};" : "=l"(w1) : "f"(wa.z), "f"(wa.w));
                asm("mov.b64 %0, {%1,%2};" : "=l"(w2) : "f"(wb.x), "f"(wb.y));
                asm("mov.b64 %0, {%1,%2};" : "=l"(w3) : "f"(wb.z), "f"(wb.w));
                asm("mov.b64 %0, {%1,%2};" : "=l"(w4p) : "f"(w8), "f"(0.0f));
                #pragma unroll
                for (int r = 0; r < 4; r++) {
                    float xv = (d == 0) ? xr[r].x : (d == 1) ? xr[r].y
                             : (d == 2) ? xr[r].z : xr[r].w;
                    unsigned long long x2;
                    asm("mov.b64 %0, {%1,%1};" : "=l"(x2) : "f"(xv));
                    asm("fma.rn.f32x2 %0, %1, %2, %0;" : "+l"(acc[r][0]) : "l"(x2), "l"(w0));
                    asm("fma.rn.f32x2 %0, %1, %2, %0;" : "+l"(acc[r][1]) : "l"(x2), "l"(w1));
                    asm("fma.rn.f32x2 %0, %1, %2, %0;" : "+l"(acc[r][2]) : "l"(x2), "l"(w2));
                    asm("fma.rn.f32x2 %0, %1, %2, %0;" : "+l"(acc[r][3]) : "l"(x2), "l"(w3));
                    asm("fma.rn.f32x2 %0, %1, %2, %0;" : "+l"(acc[r][4]) : "l"(x2), "l"(w4p));
                }
            }
        }

        #pragma unroll
        for (int r = 0; r < 4; r++) {
            float a[9];
            #pragma unroll
            for (int p = 0; p < 4; p++) {
                float lo, hi;
                asm("mov.b64 {%0,%1}, %2;" : "=f"(lo), "=f"(hi) : "l"(acc[r][p]));
                a[2 * p] = lo; a[2 * p + 1] = hi;
            }
            { float lo, hi;
              asm("mov.b64 {%0,%1}, %2;" : "=f"(lo), "=f"(hi) : "l"(acc[r][4]));
              a[8] = lo; (void)hi; }
            #pragma unroll
            for (int l = 0; l < 9; l++) {
                float v = a[l];
                v += __shfl_xor_sync(0xffffffffu, v, 16);
                v += __shfl_xor_sync(0xffffffffu, v, 8);
                v += __shfl_xor_sync(0xffffffffu, v, 4);
                v += __shfl_xor_sync(0xffffffffu, v, 2);
                v += __shfl_xor_sync(0xffffffffu, v, 1);
                a[l] = v;
            }
            if (lane < LL)
                g_logits[(size_t)(row0 + r) * LL + lane] = a[lane] + G->bs[lane];
        }

        __threadfence();
        __syncthreads();
        if (tid == 0) *((volatile int*)&g_flag[bb * 16 + c]) = 1;
        return;
    }

    // ==================== CRF role ====================
    CrfSmem* S = (CrfSmem*)smem_raw;
    int b = bid;
    int sl = seqlen[b];

    if (tid < 16) S->s_cflag[tid] = 0;
    if (tid < LL * LL) S->Ts[tid] = trans[tid];
    if (tid >= 128 && tid < 128 + 108) {
        int k = tid - 128, i = k / 12, m = k - i * 12;
        S->sPp[k] = (m < 9) ? ex2f_(trans[i * LL + m] * LOG2E) : 0.0f;
    }
    __syncthreads();

    int j = (lane < LL) ? lane : (LL - 1);
    volatile int* cf = (volatile int*)S->s_cflag;

    if (warp == 0) {
        // ===== chain: exact serial Viterbi, chunk-synchronous =====
        float Tj[9];
        #pragma unroll
        for (int i = 0; i < 9; i++) Tj[i] = S->Ts[i * LL + j];

        // chunk 0
        while (cf[0] == 0) {}
        __threadfence_block();
        S->astore[j] = S->slog[j];
        #pragma unroll 4
        for (int t = 1; t < 32; t++) {
            const float* prow = S->astore + (t - 1) * AST;
            float4 r0 = *(const float4*)(prow);
            float4 r1 = *(const float4*)(prow + 4);
            float  a8 = prow[8];
            float w = S->slog[t * LL + j];
            float m = fmaxf(fmaxf(fmaxf(r0.x + Tj[0], r0.y + Tj[1]),
                                  fmaxf(r0.z + Tj[2], r0.w + Tj[3])),
                            fmaxf(fmaxf(fmaxf(r1.x + Tj[4], r1.y + Tj[5]),
                                        fmaxf(r1.z + Tj[6], r1.w + Tj[7])),
                                  a8 + Tj[8]));
            S->astore[t * AST + j] = m + w;
        }
        for (int c = 1; c < 16; c++) {
            while (cf[c] == 0) {}
            __threadfence_block();
            int base = c * 32;
            #pragma unroll 4
            for (int tt = 0; tt < 32; tt++) {
                int t = base + tt;
                const float* prow = S->astore + (t - 1) * AST;
                float4 r0 = *(const float4*)(prow);
                float4 r1 = *(const float4*)(prow + 4);
                float  a8 = prow[8];
                float w = S->slog[t * LL + j];
                float m = fmaxf(fmaxf(fmaxf(r0.x + Tj[0], r0.y + Tj[1]),
                                      fmaxf(r0.z + Tj[2], r0.w + Tj[3])),
                                fmaxf(fmaxf(fmaxf(r1.x + Tj[4], r1.y + Tj[5]),
                                            fmaxf(r1.z + Tj[6], r1.w + Tj[7])),
                                      a8 + Tj[8]));
                S->astore[t * AST + j] = m + w;
            }
        }
        const float* af = S->astore + (sl - 1) * AST;
        float best = af[0];
        int last = 0;
        #pragma unroll
        for (int i = 1; i < 9; i++) {
            float v = af[i];
            if (v > best) { best = v; last = i; }
        }
        if (lane == 0) S->s_lasti = last;
    } else if (warp <= 3) {
        // ===== chunk-parallel logZ (P from smem, padded rows) =====
        int wl = tid - 32;               // warp1:0-31, warp2:32-63, warp3:64-95
        int g = wl / 9, cj = wl - 9 * g;
        int needc = (warp == 1) ? 7 : (warp == 2) ? 13 : 15;
        while (cf[needc] == 0) __nanosleep(100);
        __threadfence_block();

        int NS = sl - 1;
        int Cs = (NS + NG - 1) / NG;
        int t0 = 1 + g * Cs;
        int t1 = min(t0 + Cs, sl);

        if (wl < 90) {
            float v[9];
            int E = 0;
            if (Cs > 0 && t0 < t1) {
                const float* w0 = S->swexp + t0 * LL;
                const float* Pc = S->sPp + cj * 12;
                #pragma unroll
                for (int m = 0; m < 9; m++) v[m] = w0[m] * Pc[m];
                for (int t = t0 + 1; t < t1; t++) {
                    const float* wt = S->swexp + t * LL;
                    float nv[9];
                    #pragma unroll
                    for (int m = 0; m < 9; m++) nv[m] = 0.0f;
                    #pragma unroll
                    for (int i = 0; i < 9; i++) {
                        const float* Pi = S->sPp + i * 12;
                        float4 p0 = *(const float4*)(Pi);
                        float4 p1 = *(const float4*)(Pi + 4);
                        float  p8 = Pi[8];
                        float vi = v[i];
                        nv[0] = fmaf(vi, p0.x, nv[0]);
                        nv[1] = fmaf(vi, p0.y, nv[1]);
                        nv[2] = fmaf(vi, p0.z, nv[2]);
                        nv[3] = fmaf(vi, p0.w, nv[3]);
                        nv[4] = fmaf(vi, p1.x, nv[4]);
                        nv[5] = fmaf(vi, p1.y, nv[5]);
                        nv[6] = fmaf(vi, p1.z, nv[6]);
                        nv[7] = fmaf(vi, p1.w, nv[7]);
                        nv[8] = fmaf(vi, p8,   nv[8]);
                    }
                    #pragma unroll
                    for (int m = 0; m < 9; m++) nv[m] *= wt[m];
                    unsigned bits = __float_as_uint(nv[0]);
                    int e = (int)(bits >> 23) - 127;
                    E += e;
                    float factor = __uint_as_float((unsigned)(127 - e) << 23);
                    #pragma unroll
                    for (int m = 0; m < 9; m++) v[m] = nv[m] * factor;
                }
            } else {
                #pragma unroll
                for (int m = 0; m < 9; m++) v[m] = (m == cj) ? 1.0f : 0.0f;
                E = 0;
            }
            S->sE[g][cj] = E;
            #pragma unroll
            for (int m = 0; m < 9; m++) S->sM[g][m][cj] = v[m];
        }
        asm volatile("bar.sync 1, 96;" ::: "memory");
        if (wl < 90) {
            int Emax = S->sE[g][0];
            #pragma unroll
            for (int i = 1; i < 9; i++) Emax = max(Emax, S->sE[g][i]);
            int E = S->sE[g][cj];
            int d = E - Emax;
            float adj = (d < -120) ? 0.0f : __uint_as_float((unsigned)(127 + d) << 23);
            #pragma unroll
            for (int m = 0; m < 9; m++) S->sM[g][m][cj] *= adj;
            if (cj == 0) S->sEg[g] = Emax;
        }
        asm volatile("bar.sync 1, 96;" ::: "memory");

        if (warp == 1) {
            float p0 = S->slog[0] * LOG2E;
            float alpha = ex2f_(S->slog[j] * LOG2E - p0);
            int A = 0;
            for (int g2 = 0; g2 < NG; g2++) {
                float av2[9];
                #pragma unroll
                for (int i = 0; i < 9; i++) av2[i] = __shfl_sync(0xffffffffu, alpha, i);
                float s = S->sM[g2][j][0] * av2[0];
                #pragma unroll
                for (int i2 = 1; i2 < 9; i2++)
                    s = fmaf(S->sM[g2][j][i2], av2[i2], s);
                float s0 = __shfl_sync(0xffffffffu, s, 0);
                unsigned bits = __float_as_uint(s0);
                int e = (int)(bits >> 23) - 127;
                A += e + S->sEg[g2];
                float factor = __uint_as_float((unsigned)(127 - e) << 23);
                alpha = s * factor;
            }
            float cv[9];
            #pragma unroll
            for (int i = 0; i < 9; i++) cv[i] = __shfl_sync(0xffffffffu, alpha, i);
            float sum = ((cv[0] + cv[1]) + (cv[2] + cv[3]))
                      + (((cv[4] + cv[5]) + (cv[6] + cv[7])) + cv[8]);
            float logZ = (lg2f_(sum) + (float)A + p0) * LN2;
            if (lane == 0) S->s_logZ = logZ;
            __syncwarp();

            const int* lab = label + b * TT;
            float sc = 0.0f;
            for (int t = lane; t < sl; t += 32) {
                int lt = lab[t];
                sc += S->slog[t * LL + lt];
                if (t > 0) sc += S->Ts[lab[t - 1] * LL + lt];
            }
            sc = wredf(sc);
            if (lane == 0) g_ll[b] = S->s_logZ - sc;
        }
    } else {
        // ===== staging warps (4-7): global flags -> smem chunks =====
        for (int c = warp - 4; c < 16; c += 4) {
            volatile int* gf = (volatile int*)&g_flag[b * 16 + c];
            while (*gf == 0) __nanosleep(100);
            __threadfence();
            const float4* src = (const float4*)g_logits + (size_t)b * 1152 + c * 72;
            float4* d1 = (float4*)S->slog + c * 72;
            float4* d2 = (float4*)S->swexp + c * 72;
            #pragma unroll
            for (int i = lane; i < 72; i += 32) {
                float4 v = src[i];
                d1[i] = v;
                float4 e;
                e.x = ex2f_(v.x * LOG2E); e.y = ex2f_(v.y * LOG2E);
                e.z = ex2f_(v.z * LOG2E); e.w = ex2f_(v.w * LOG2E);
                d2[i] = e;
            }
            __syncwarp();
            __threadfence_block();
            if (lane == 0) *((volatile int*)&S->s_cflag[c]) = 1;
        }
    }
    __syncthreads();

    // ---- parallel backpointer recompute (252 threads, 28 groups) ----
    if (tid < 252) {
        int jj = tid % 9, g = tid / 9;
        float Tc[9];
        #pragma unroll
        for (int i = 0; i < 9; i++) Tc[i] = S->Ts[i * LL + jj];
        for (int t = 1 + g; t < sl; t += 28) {
            const float* ap = S->astore + (t - 1) * AST;
            float bv = ap[0] + Tc[0];
            int bi = 0;
            #pragma unroll
            for (int i = 1; i < 9; i++) {
                float v = ap[i] + Tc[i];
                if (v > bv) { bv = v; bi = i; }
            }
            S->sbp[t * LL + jj] = (unsigned char)bi;
        }
    }
    __syncthreads();

    int last = S->s_lasti;
    for (int t = sl - 1 + tid; t < TT; t += 256) S->stag[t] = (unsigned char)last;

    // ---- parallel backtrace via map suffix-scan (warp 0) ----
    if (warp == 0 && sl > 1) {
        int N = sl - 1;
        int C = (N + 31) >> 5;
        int a0 = 1 + lane * C;
        int b0 = min(a0 + C, sl);
        unsigned long long Pm = MAP_IDENTITY;
        for (int m = a0; m < b0; m++) {
            const unsigned char* row = S->sbp + m * LL;
            unsigned long long f = 0;
            #pragma unroll
            for (int i = 0; i < 9; i++)
                f |= (unsigned long long)row[i] << (4 * i);
            Pm = map_compose(Pm, f);
        }
        #pragma unroll
        for (int off = 1; off < 32; off <<= 1) {
            unsigned long long q = __shfl_down_sync(0xffffffffu, Pm, off);
            if (lane + off < 32) Pm = map_compose(Pm, q);
        }
        unsigned long long R = __shfl_down_sync(0xffffffffu, Pm, 1);
        if (lane == 31) R = MAP_IDENTITY;
        if (a0 < sl) {
            int xcur = (int)((R >> (4 * last)) & 15ull);
            for (int m = b0 - 1; m >= a0; m--) {
                xcur = S->sbp[m * LL + xcur];
                S->stag[m - 1] = (unsigned char)xcur;
            }
        }
    }
    __syncthreads();

    // ---- vit output + fused metrics ----
    float* vout = outF + b * TT;
    const int* lab = label + b * TT;
    int tp = 0, tn = 0, fp = 0, corr = 0;
    for (int i = tid; i < TT; i += 256) {
        int vi = S->stag[i];
        vout[i] = (float)vi;
        int la = lab[i];
        if (la > 0) { if (vi == la) tp++; else tn++; }   // unmasked, per reference
        if (i < sl) {
            if (vi == la) corr++;
            if (la == 0 && vi > 0) fp++;
        }
    }
    tp = wredi(tp); tn = wredi(tn); fp = wredi(fp); corr = wredi(corr);
    if (lane == 0) {
        S->sh_m[0][warp] = tp; S->sh_m[1][warp] = tn;
        S->sh_m[2][warp] = fp; S->sh_m[3][warp] = corr;
    }
    __syncthreads();
    if (warp == 0) {
        int a0 = (lane < 8) ? S->sh_m[0][lane] : 0;
        int a1 = (lane < 8) ? S->sh_m[1][lane] : 0;
        int a2 = (lane < 8) ? S->sh_m[2][lane] : 0;
        int a3 = (lane < 8) ? S->sh_m[3][lane] : 0;
        a0 = wredi(a0); a1 = wredi(a1); a2 = wredi(a2); a3 = wredi(a3);
        if (lane == 0) {
            g_part[b][0] = (float)a0;
            g_part[b][1] = (float)a1;
            g_part[b][2] = (float)a2;
            g_part[b][3] = (float)a3;
        }
    }

    // ---- completion ticket; last block writes scalars + resets state ----
    __threadfence();
    __syncthreads();
    if (tid == 0) {
        int old = atomicAdd(&g_tick, 1);
        S->s_isLast = (old == BB - 1);
    }
    __syncthreads();
    if (S->s_isLast && warp == 0) {
        __threadfence();
        float lsum = g_ll[lane] + g_ll[lane + 32];
        int sls = seqlen[lane] + seqlen[lane + 32];
        float m0 = g_part[lane][0] + g_part[lane + 32][0];
        float m1 = g_part[lane][1] + g_part[lane + 32][1];
        float m2 = g_part[lane][2] + g_part[lane + 32][2];
        float m3 = g_part[lane][3] + g_part[lane + 32][3];
        lsum = wredf(lsum);
        sls = wredi(sls);
        m0 = wredf(m0); m1 = wredf(m1); m2 = wredf(m2); m3 = wredf(m3);
        for (int i = lane; i < BB * 16; i += 32) g_flag[i] = 0;   // reset for replay
        if (lane == 0) {
            outF[BB * TT + 0] = m0;                    // tp
            outF[BB * TT + 1] = m1;                    // tn
            outF[BB * TT + 2] = m2;                    // fp
            outF[BB * TT + 3] = lsum / (float)BB;      // loss
            outF[BB * TT + 4] = m3 / (float)sls;       // accuracy
            g_tick = 0;
        }
    }
}

// ---------------------------------------------------------------------------
extern "C" void kernel_launch(void* const* d_in, const int* in_sizes, int n_in,
                              void* d_out, int out_size) {
    const float* x      = (const float*)d_in[0];
    const float* W      = (const float*)d_in[1];
    const float* bias   = (const float*)d_in[2];
    const float* trans  = (const float*)d_in[3];
    const int*   label  = (const int*)d_in[4];
    const int*   seqlen = (const int*)d_in[5];
    float* out = (float*)d_out;

    static int smem_set = 0;
    if (!smem_set) {
        cudaFuncSetAttribute(fused_kernel,
                             cudaFuncAttributeMaxDynamicSharedMemorySize,
                             (int)sizeof(CrfSmem));
        smem_set = 1;
    }

    fused_kernel<<<BB + NGEMM, 256, sizeof(CrfSmem)>>>(x, W, bias, trans,
                                                       label, seqlen, out);
}